// round 15
// baseline (speedup 1.0000x reference)
#include <cuda_runtime.h>
#include <cuda_fp16.h>
#include <cstdint>

#define DN 128              // embedding dim
#define MAXN 200002         // USERS + ITEMS
#define MAXNNZ 2000000      // 2 * E

#define SCAN_BLK 256
#define SCAN_IPT 16
#define SCAN_CHUNK (SCAN_BLK * SCAN_IPT)   // 4096
#define MAX_SCAN_BLOCKS 64                 // ceil(200002/4096) = 49

// ---- static device scratch (no allocation allowed) ----
__device__ __half g_xe[(size_t)MAXN * DN];    // emb in fp16
__device__ __half g_x1[(size_t)MAXN * DN];    // layer-1 out
__device__ __half g_x2[(size_t)MAXN * DN];    // layer-2 out
__device__ int   g_deg[MAXN];
__device__ int   g_rowptr[MAXN];
__device__ int   g_cursor[MAXN];
__device__ unsigned long long g_scan_state[MAX_SCAN_BLOCKS]; // bit63=published, low=aggregate
__device__ int2  g_edge[MAXNNZ];              // (col, float_bits(val)) grouped by row

// ---------------------------------------------------------------------------
// zero: deg counters + scan state
// ---------------------------------------------------------------------------
__global__ void zero_kernel(int n) {
    int i = blockIdx.x * blockDim.x + threadIdx.x;
    if (i < n) g_deg[i] = 0;
    if (i < MAX_SCAN_BLOCKS) g_scan_state[i] = 0ull;
}

// ---------------------------------------------------------------------------
// fused: blocks [0, ew_blocks) convert emb f32->f16; the rest histogram rows
// 4 edges per thread (block-chunked, coalesced; MLP=4 on the atomics).
// ---------------------------------------------------------------------------
__global__ void f2h_hist_kernel(const float4* __restrict__ src,
                                uint2* __restrict__ dst, int total4,
                                int ew_blocks,
                                const int* __restrict__ rows, int nnz) {
    if (blockIdx.x < (unsigned)ew_blocks) {
        int i = blockIdx.x * blockDim.x + threadIdx.x;
        if (i >= total4) return;
        float4 v = src[i];
        __half2 a = __float22half2_rn(make_float2(v.x, v.y));
        __half2 b = __float22half2_rn(make_float2(v.z, v.w));
        uint2 r;
        r.x = *reinterpret_cast<unsigned int*>(&a);
        r.y = *reinterpret_cast<unsigned int*>(&b);
        dst[i] = r;
    } else {
        int base = (blockIdx.x - ew_blocks) * (blockDim.x * 4) + threadIdx.x;
        int r[4];
#pragma unroll
        for (int j = 0; j < 4; j++) {
            int e = base + j * blockDim.x;
            r[j] = (e < nnz) ? __ldg(rows + e) : -1;
        }
#pragma unroll
        for (int j = 0; j < 4; j++)
            if (r[j] >= 0) atomicAdd(&g_deg[r[j]], 1);
    }
}

// ---------------------------------------------------------------------------
// single-pass exclusive scan of g_deg -> g_rowptr/g_cursor (decoupled lookback)
// ---------------------------------------------------------------------------
__global__ void scan_fused_kernel(int n) {
    int tid = threadIdx.x, b = blockIdx.x;
    int base = b * SCAN_CHUNK + tid * SCAN_IPT;
    int local[SCAN_IPT];
    int sum = 0;
#pragma unroll
    for (int i = 0; i < SCAN_IPT; i++) {
        int idx = base + i;
        int v = (idx < n) ? g_deg[idx] : 0;
        local[i] = sum;        // exclusive within thread
        sum += v;
    }
    int lane = tid & 31, wid = tid >> 5;
    int v = sum;
#pragma unroll
    for (int o = 1; o < 32; o <<= 1) {
        int t = __shfl_up_sync(0xFFFFFFFFu, v, o);
        if (lane >= o) v += t;
    }
    __shared__ int wsum[SCAN_BLK / 32];
    __shared__ int s_base;
    if (lane == 31) wsum[wid] = v;
    __syncthreads();
    if (tid < SCAN_BLK / 32) {
        int w = wsum[tid];
#pragma unroll
        for (int o = 1; o < SCAN_BLK / 32; o <<= 1) {
            int t = __shfl_up_sync(0xFFu, w, o);
            if (tid >= o) w += t;
        }
        wsum[tid] = w;
        if (tid == SCAN_BLK / 32 - 1) {
            atomicExch(&g_scan_state[b], (1ull << 63) | (unsigned long long)(unsigned)w);
        }
    }
    __syncthreads();
    if (wid == 0) {
        unsigned long long acc = 0;
        for (int i = lane; i < b; i += 32) {
            unsigned long long st;
            do {
                st = atomicAdd(&g_scan_state[i], 0ull);
            } while (!(st >> 63));
            acc += st & 0x7FFFFFFFFFFFFFFFull;
        }
#pragma unroll
        for (int o = 16; o > 0; o >>= 1)
            acc += __shfl_down_sync(0xFFFFFFFFu, acc, o);
        if (lane == 0) s_base = (int)acc;
    }
    __syncthreads();
    int thread_excl = v - sum + (wid ? wsum[wid - 1] : 0);
    int off = thread_excl + s_base;
#pragma unroll
    for (int i = 0; i < SCAN_IPT; i++) {
        int idx = base + i;
        if (idx < n) {
            int p = off + local[i];
            g_rowptr[idx] = p;
            g_cursor[idx] = p;
        }
    }
}

// ---------------------------------------------------------------------------
// scatter: 4 edges per thread, loads batched, atomics batched (MLP=4), stores
// batched. Block-chunked indexing keeps the edge-array loads coalesced.
// ---------------------------------------------------------------------------
__global__ void scatter_kernel(const int* __restrict__ rows,
                               const int* __restrict__ cols,
                               const float* __restrict__ vals,
                               int nnz) {
    int base = blockIdx.x * (blockDim.x * 4) + threadIdx.x;
    int r[4], c[4];
    float v[4];
#pragma unroll
    for (int j = 0; j < 4; j++) {
        int e = base + j * blockDim.x;
        if (e < nnz) {
            r[j] = __ldg(rows + e);
            c[j] = __ldg(cols + e);
            v[j] = __ldg(vals + e);
        } else {
            r[j] = -1;
        }
    }
    int pos[4];
#pragma unroll
    for (int j = 0; j < 4; j++)
        if (r[j] >= 0) pos[j] = atomicAdd(&g_cursor[r[j]], 1);
#pragma unroll
    for (int j = 0; j < 4; j++)
        if (r[j] >= 0) g_edge[pos[j]] = make_int2(c[j], __float_as_int(v[j]));
}

// ---------------------------------------------------------------------------
// pull SpMM (FROZEN round-8 shape): fp16 operand, fp32 accumulation,
// warp per row, 4-wide edge unroll (MLP=4).
// ---------------------------------------------------------------------------
__device__ __forceinline__ float2 h2f_lo(unsigned u) {
    __half2 h = *reinterpret_cast<__half2*>(&u);
    return __half22float2(h);
}

template <bool FUSE>
__global__ void __launch_bounds__(256) spmm_half_kernel(
        const uint2* __restrict__ x,
        uint2* __restrict__ yh,
        const float4* __restrict__ emb,
        const uint2* __restrict__ x1,
        const uint2* __restrict__ x2,
        float4* __restrict__ outf,
        int n) {
    int w = (blockIdx.x * blockDim.x + threadIdx.x) >> 5;
    int lane = threadIdx.x & 31;
    if (w >= n) return;

    int start = g_rowptr[w];
    int end = start + g_deg[w];

    float a0x = 0.f, a0y = 0.f, a0z = 0.f, a0w = 0.f;
    float a1x = 0.f, a1y = 0.f, a1z = 0.f, a1w = 0.f;

    int e = start;
    for (; e + 4 <= end; e += 4) {
        int2 e0 = g_edge[e];
        int2 e1 = g_edge[e + 1];
        int2 e2 = g_edge[e + 2];
        int2 e3 = g_edge[e + 3];
        uint2 m0 = __ldg(x + (size_t)e0.x * 32 + lane);
        uint2 m1 = __ldg(x + (size_t)e1.x * 32 + lane);
        uint2 m2 = __ldg(x + (size_t)e2.x * 32 + lane);
        uint2 m3 = __ldg(x + (size_t)e3.x * 32 + lane);
        float v0 = __int_as_float(e0.y);
        float v1 = __int_as_float(e1.y);
        float v2 = __int_as_float(e2.y);
        float v3 = __int_as_float(e3.y);
        {
            float2 fa = h2f_lo(m0.x), fb = h2f_lo(m0.y);
            a0x += v0 * fa.x; a0y += v0 * fa.y; a0z += v0 * fb.x; a0w += v0 * fb.y;
        }
        {
            float2 fa = h2f_lo(m1.x), fb = h2f_lo(m1.y);
            a1x += v1 * fa.x; a1y += v1 * fa.y; a1z += v1 * fb.x; a1w += v1 * fb.y;
        }
        {
            float2 fa = h2f_lo(m2.x), fb = h2f_lo(m2.y);
            a0x += v2 * fa.x; a0y += v2 * fa.y; a0z += v2 * fb.x; a0w += v2 * fb.y;
        }
        {
            float2 fa = h2f_lo(m3.x), fb = h2f_lo(m3.y);
            a1x += v3 * fa.x; a1y += v3 * fa.y; a1z += v3 * fb.x; a1w += v3 * fb.y;
        }
    }
    if (e + 2 <= end) {
        int2 e0 = g_edge[e];
        int2 e1 = g_edge[e + 1];
        uint2 m0 = __ldg(x + (size_t)e0.x * 32 + lane);
        uint2 m1 = __ldg(x + (size_t)e1.x * 32 + lane);
        float v0 = __int_as_float(e0.y);
        float v1 = __int_as_float(e1.y);
        float2 fa = h2f_lo(m0.x), fb = h2f_lo(m0.y);
        a0x += v0 * fa.x; a0y += v0 * fa.y; a0z += v0 * fb.x; a0w += v0 * fb.y;
        float2 fc = h2f_lo(m1.x), fd = h2f_lo(m1.y);
        a1x += v1 * fc.x; a1y += v1 * fc.y; a1z += v1 * fd.x; a1w += v1 * fd.y;
        e += 2;
    }
    if (e < end) {
        int2 e0 = g_edge[e];
        uint2 m0 = __ldg(x + (size_t)e0.x * 32 + lane);
        float v0 = __int_as_float(e0.y);
        float2 fa = h2f_lo(m0.x), fb = h2f_lo(m0.y);
        a0x += v0 * fa.x; a0y += v0 * fa.y; a0z += v0 * fb.x; a0w += v0 * fb.y;
    }

    float rx = a0x + a1x, ry = a0y + a1y, rz = a0z + a1z, rw = a0w + a1w;

    size_t oidx = (size_t)w * 32 + lane;
    if (FUSE) {
        float4 eb = __ldg(emb + oidx);
        uint2 u1 = __ldg(x1 + oidx);
        uint2 u2 = __ldg(x2 + oidx);
        float2 b10 = h2f_lo(u1.x), b11 = h2f_lo(u1.y);
        float2 b20 = h2f_lo(u2.x), b21 = h2f_lo(u2.y);
        float4 o;
        o.x = (rx + eb.x + b10.x + b20.x) * 0.25f;
        o.y = (ry + eb.y + b10.y + b20.y) * 0.25f;
        o.z = (rz + eb.z + b11.x + b21.x) * 0.25f;
        o.w = (rw + eb.w + b11.y + b21.y) * 0.25f;
        outf[oidx] = o;
    } else {
        __half2 ha = __float22half2_rn(make_float2(rx, ry));
        __half2 hb = __float22half2_rn(make_float2(rz, rw));
        uint2 r;
        r.x = *reinterpret_cast<unsigned int*>(&ha);
        r.y = *reinterpret_cast<unsigned int*>(&hb);
        yh[oidx] = r;
    }
}

// ---------------------------------------------------------------------------
extern "C" void kernel_launch(void* const* d_in, const int* in_sizes, int n_in,
                              void* d_out, int out_size) {
    const float* emb  = (const float*)d_in[0];
    const float* vals = (const float*)d_in[1];
    const int*   rows = (const int*)d_in[2];
    const int*   cols = (const int*)d_in[3];
    float* out = (float*)d_out;

    int nnz = in_sizes[1];
    int n   = in_sizes[0] / DN;

    __half* xe; __half* x1; __half* x2;
    cudaGetSymbolAddress((void**)&xe, g_xe);
    cudaGetSymbolAddress((void**)&x1, g_x1);
    cudaGetSymbolAddress((void**)&x2, g_x2);

    const int TB = 256;
    int total4 = in_sizes[0] / 4;
    int nb_scan      = (n + SCAN_CHUNK - 1) / SCAN_CHUNK;
    int deg_blocks   = (n + TB - 1) / TB;
    int edge_blocks4 = (nnz + TB * 4 - 1) / (TB * 4);
    int ew_blocks    = (total4 + TB - 1) / TB;
    int spmm_blocks  = (n * 32 + TB - 1) / TB;

    // --- CSR build + f2h ---
    zero_kernel<<<deg_blocks, TB>>>(n);
    f2h_hist_kernel<<<ew_blocks + edge_blocks4, TB>>>(
        (const float4*)emb, (uint2*)xe, total4, ew_blocks, rows, nnz);
    scan_fused_kernel<<<nb_scan, SCAN_BLK>>>(n);
    scatter_kernel<<<edge_blocks4, TB>>>(rows, cols, vals, nnz);

    // --- 3 layers (frozen SpMM) ---
    spmm_half_kernel<false><<<spmm_blocks, TB>>>(
        (const uint2*)xe, (uint2*)x1, nullptr, nullptr, nullptr, nullptr, n);
    spmm_half_kernel<false><<<spmm_blocks, TB>>>(
        (const uint2*)x1, (uint2*)x2, nullptr, nullptr, nullptr, nullptr, n);
    spmm_half_kernel<true><<<spmm_blocks, TB>>>(
        (const uint2*)x2, nullptr,
        (const float4*)emb, (const uint2*)x1, (const uint2*)x2,
        (float4*)out, n);
}